// round 5
// baseline (speedup 1.0000x reference)
#include <cuda_runtime.h>

// Adaptive threshold spike encoding — persistent exact-fit grid.
// x: [B=32, F=65536] f32.  out: [B=32, T=32, F=65536] f32.
// Grid = 148 SMs * 8 resident CTAs = 1184 blocks x 256 threads; each block
// grid-strides over the 2048 tiles of 256 float4. Removes the partial second
// wave / wave-transition of the 2048-block launch. Stores remain coalesced
// STG.128 with evict-first policy (best measured path; DRAM-drain bound).

#define TIMESTEPS 32
#define F_DIM 65536
#define F4_DIM (F_DIM / 4)       // 16384 float4 per feature row
#define RATE 0.1f
#define OMR 0.9f
#define THR0 0.5f
#define THREADS 256
#define GRID_BLOCKS 1184         // 148 * 8, one full resident wave
#define TILES 2048               // 524288 float4 / 256 threads

__global__ __launch_bounds__(THREADS)
void spike_persistent_kernel(const float4* __restrict__ x,
                             float4* __restrict__ out) {
    int tid = threadIdx.x;

    for (int tile = blockIdx.x; tile < TILES; tile += GRID_BLOCKS) {
        int i = tile * THREADS + tid;        // float4 index

        float4 xv = __ldcs(&x[i]);

        int e  = i << 2;                     // element index of lane 0
        int b  = e >> 16;                    // batch  (e / 65536)
        int f4 = (e & (F_DIM - 1)) >> 2;     // float4 slot within feature row

        float xx[4] = {xv.x, xv.y, xv.z, xv.w};
        float ad[4], acc[4], thr[4];
#pragma unroll
        for (int l = 0; l < 4; l++) {
            ad[l]  = RATE * fabsf(xx[l]);
            acc[l] = 0.0f;
            thr[l] = THR0;
        }

        float4* ob = out + (size_t)b * (TIMESTEPS * F4_DIM) + f4;

#pragma unroll
        for (int t = 0; t < TIMESTEPS; t++) {
            float s[4];
#pragma unroll
            for (int l = 0; l < 4; l++) {
                acc[l] = acc[l] + xx[l];
                bool m = (acc[l] >= thr[l]);
                s[l]   = m ? 1.0f : 0.0f;
                acc[l] = m ? 0.0f : acc[l];
                thr[l] = thr[l] * OMR + ad[l];
            }
            float4 sv;
            sv.x = s[0]; sv.y = s[1]; sv.z = s[2]; sv.w = s[3];
            __stcs(ob + (size_t)t * F4_DIM, sv);
        }
    }
}

extern "C" void kernel_launch(void* const* d_in, const int* in_sizes, int n_in,
                              void* d_out, int out_size) {
    const float4* x = (const float4*)d_in[0];
    float4* out = (float4*)d_out;
    spike_persistent_kernel<<<GRID_BLOCKS, THREADS>>>(x, out);
}

// round 6
// speedup vs baseline: 1.0758x; 1.0758x over previous
#include <cuda_runtime.h>

// Adaptive threshold spike encoding — best-known config (R3) with 512-thread
// blocks: 1024 blocks x 512 threads, one float4 per thread, 32 regs,
// coalesced STG.128 evict-first stores. 8 KB contiguous per CTA per
// timestep plane.
// x: [B=32, F=65536] f32.  out: [B=32, T=32, F=65536] f32.

#define TIMESTEPS 32
#define F_DIM 65536
#define F4_DIM (F_DIM / 4)      // 16384 float4 per feature row
#define RATE 0.1f
#define OMR 0.9f
#define THR0 0.5f
#define THREADS 512

__global__ __launch_bounds__(THREADS)
void adaptive_threshold_kernel(const float4* __restrict__ x,
                               float4* __restrict__ out) {
    int i = blockIdx.x * THREADS + threadIdx.x;   // float4 index

    float4 xv = __ldcs(&x[i]);

    // element index -> (batch, feature4)
    int e  = i << 2;                 // element index of lane 0 of this float4
    int b  = e >> 16;                // / 65536
    int f4 = (e & (F_DIM - 1)) >> 2;

    float xx[4] = {xv.x, xv.y, xv.z, xv.w};
    float ad[4], acc[4], thr[4];
#pragma unroll
    for (int l = 0; l < 4; l++) {
        ad[l]  = RATE * fabsf(xx[l]);
        acc[l] = 0.0f;
        thr[l] = THR0;
    }

    // out[b][t][f] : base of this (b, f4) column, stride F4_DIM per timestep
    float4* ob = out + (size_t)b * (TIMESTEPS * F4_DIM) + f4;

#pragma unroll
    for (int t = 0; t < TIMESTEPS; t++) {
        float s[4];
#pragma unroll
        for (int l = 0; l < 4; l++) {
            acc[l] = acc[l] + xx[l];
            bool m = (acc[l] >= thr[l]);
            s[l]   = m ? 1.0f : 0.0f;
            acc[l] = m ? 0.0f : acc[l];
            thr[l] = thr[l] * OMR + ad[l];
        }
        float4 sv;
        sv.x = s[0]; sv.y = s[1]; sv.z = s[2]; sv.w = s[3];
        __stcs(ob + (size_t)t * F4_DIM, sv);
    }
}

extern "C" void kernel_launch(void* const* d_in, const int* in_sizes, int n_in,
                              void* d_out, int out_size) {
    const float4* x = (const float4*)d_in[0];
    float4* out = (float4*)d_out;
    int n4 = in_sizes[0] / 4;              // 524,288
    int blocks = n4 / THREADS;             // 1024
    adaptive_threshold_kernel<<<blocks, THREADS>>>(x, out);
}

// round 7
// speedup vs baseline: 1.0922x; 1.0152x over previous
#include <cuda_runtime.h>

// Adaptive threshold spike encoding — final (write-bandwidth floor).
// x: [B=32, F=65536] f32.  out: [B=32, T=32, F=65536] f32.
//
// Measured conclusion across 5 configs (STG / STG.cs / TMA bulk / persistent /
// 512-thread blocks): all land at 41.8-44.2 us kernel, ~5.2 TB/s DRAM.
// The op writes 256 MB of f32 spikes; the sustained HBM3e write-drain rate
// (~5.2 TB/s, below the 8 TB/s read spec) is the hard floor. Best shape:
// 2048 blocks x 256 threads, one float4 per thread, 32 regs, coalesced
// STG.128 evict-first stores.

#define TIMESTEPS 32
#define F_DIM 65536
#define F4_DIM (F_DIM / 4)      // 16384 float4 per feature row
#define RATE 0.1f
#define OMR 0.9f
#define THR0 0.5f
#define THREADS 256

__global__ __launch_bounds__(THREADS)
void adaptive_threshold_kernel(const float4* __restrict__ x,
                               float4* __restrict__ out) {
    int i = blockIdx.x * THREADS + threadIdx.x;   // float4 index (exact fit)

    float4 xv = __ldcs(&x[i]);

    // element index -> (batch, feature4)
    int e  = i << 2;                 // element index of lane 0 of this float4
    int b  = e >> 16;                // batch = e / 65536
    int f4 = (e & (F_DIM - 1)) >> 2; // float4 slot within the feature row

    float xx[4] = {xv.x, xv.y, xv.z, xv.w};
    float ad[4], acc[4], thr[4];
#pragma unroll
    for (int l = 0; l < 4; l++) {
        ad[l]  = RATE * fabsf(xx[l]);
        acc[l] = 0.0f;
        thr[l] = THR0;
    }

    // out[b][t][f]: base of this (b, f4) column, stride F4_DIM per timestep
    float4* ob = out + (size_t)b * (TIMESTEPS * F4_DIM) + f4;

#pragma unroll
    for (int t = 0; t < TIMESTEPS; t++) {
        float s[4];
#pragma unroll
        for (int l = 0; l < 4; l++) {
            acc[l] = acc[l] + xx[l];
            bool m = (acc[l] >= thr[l]);
            s[l]   = m ? 1.0f : 0.0f;
            acc[l] = m ? 0.0f : acc[l];
            thr[l] = thr[l] * OMR + ad[l];
        }
        float4 sv;
        sv.x = s[0]; sv.y = s[1]; sv.z = s[2]; sv.w = s[3];
        __stcs(ob + (size_t)t * F4_DIM, sv);
    }
}

extern "C" void kernel_launch(void* const* d_in, const int* in_sizes, int n_in,
                              void* d_out, int out_size) {
    const float4* x = (const float4*)d_in[0];
    float4* out = (float4*)d_out;
    int n4 = in_sizes[0] / 4;              // 524,288 — divisible by THREADS
    int blocks = n4 / THREADS;             // 2048
    adaptive_threshold_kernel<<<blocks, THREADS>>>(x, out);
}